// round 7
// baseline (speedup 1.0000x reference)
#include <cuda_runtime.h>
#include <math.h>
#include <stdint.h>

#define B_   4096
#define J_   32
#define E_   256
#define ROWS (B_ * J_)

// ======================= scratch (device globals) ==========================
__device__ float g_c1[B_ * E_];     // bias + x @ W^T
__device__ float g_c2[J_ * E_];     // keys @ V^T
__device__ float g_xk[B_ * J_];     // x . key_j   (raw dot, pre-sigmoid)

// ======================= PTX helpers =======================================
__device__ __forceinline__ uint32_t smem_u32(const void* p) {
    uint32_t a;
    asm("{ .reg .u64 t; cvta.to.shared.u64 t, %1; cvt.u32.u64 %0, t; }"
        : "=r"(a) : "l"(p));
    return a;
}

#define CP_ASYNC16(dst, src)                                                  \
    asm volatile("cp.async.cg.shared.global [%0], [%1], 16;"                  \
        :: "r"(dst), "l"(__cvta_generic_to_global((const void*)(src))) : "memory")
#define CP_COMMIT() asm volatile("cp.async.commit_group;" ::: "memory")
#define CP_WAIT1()  asm volatile("cp.async.wait_group 1;" ::: "memory")
#define CP_WAIT0()  asm volatile("cp.async.wait_group 0;" ::: "memory")

__device__ __forceinline__ void mma_tf32(float* d, const uint32_t* a,
                                         const uint32_t* b) {
    asm volatile(
        "mma.sync.aligned.m16n8k8.row.col.f32.tf32.tf32.f32 "
        "{%0,%1,%2,%3}, {%4,%5,%6,%7}, {%8,%9}, {%0,%1,%2,%3};"
        : "+f"(d[0]), "+f"(d[1]), "+f"(d[2]), "+f"(d[3])
        : "r"(a[0]), "r"(a[1]), "r"(a[2]), "r"(a[3]), "r"(b[0]), "r"(b[1]));
}

__device__ __forceinline__ void ldsm_x4(uint32_t* r, uint32_t addr) {
    asm volatile("ldmatrix.sync.aligned.m8n8.x4.shared.b16 {%0,%1,%2,%3}, [%4];"
        : "=r"(r[0]), "=r"(r[1]), "=r"(r[2]), "=r"(r[3]) : "r"(addr));
}
__device__ __forceinline__ void ldsm_x2(uint32_t* r, uint32_t addr) {
    asm volatile("ldmatrix.sync.aligned.m8n8.x2.shared.b16 {%0,%1}, [%2];"
        : "=r"(r[0]), "=r"(r[1]) : "r"(addr));
}

// ======================= shared GEMM config ================================
// 512 thr (16 warps, 4m x 4n), warp tile 32x64. CTA tile M=128, N=256,
// K=256 in 8 chunks of 32. A resident (pitch 260, raw fp32 -> HW tf32
// truncation). B double-buffered raw fp32 via cp.async (pitch 36, k LOCAL
// to the 32-wide stage). Fragments via ldmatrix (pitches == 4 mod 32).
#define PA    260
#define PB    36
#define AF    33280                  // 128*260 floats; B stages follow
#define BSF   9216                   // 256*36 floats per stage
#define XF    (AF + 2 * BSF)         // 51712 : x tile (4x256) / bias
#define GF    (XF + 1024)            // 52736 : gate[128]
#define REDF  (GF + 128)             // 52864 : red[128*4]
#define INVF  (REDF + 512)           // 53376 : inv[128]
#define SMEMF (INVF + 128)           // 53504 floats
#define MAIN_SMEM (SMEMF * 4)        // 214016 bytes

// Stage the 128x256 A tile via cp.async (512 threads).
__device__ __forceinline__ void stage_a(const float* __restrict__ Ag,
                                        int row0, uint32_t sb, int tid)
{
    #pragma unroll
    for (int i = 0; i < 16; ++i) {
        int idx = tid + (i << 9);
        int r = idx >> 6, c4 = idx & 63;
        CP_ASYNC16(sb + (uint32_t)(r * PA + c4 * 4) * 4u,
                   Ag + (size_t)(row0 + r) * E_ + c4 * 4);
    }
}

// Mainloop: acc += A_tile @ Bg^T  (Bg is 256x256 row-major [n][k]).
// Caller must have issued A staging cp.asyncs (uncommitted).
__device__ __forceinline__ void tf32_mainloop(const float* __restrict__ Bg,
    uint32_t sb, int tid, float acc[2][8][4])
{
    const int lane = tid & 31;
    const int wid  = tid >> 5;
    const int mwarp = wid >> 2;       // 0..3 (32 rows)
    const int nwarp = wid & 3;        // 0..3 (64 cols)

    // ldmatrix lane-address bases (bytes)
    const uint32_t a_base = sb
        + (uint32_t)((mwarp * 32 + (lane & 15)) * PA + ((lane >> 4) << 2)) * 4u;
    const uint32_t b_lane =
        (uint32_t)((nwarp * 64 + (lane & 7)) * PB + (((lane >> 3) & 1) << 2)) * 4u;

    #pragma unroll
    for (int i = 0; i < 4; ++i) {                       // B chunk 0
        int idx = tid + (i << 9);
        int f = idx >> 3, k4 = idx & 7;
        CP_ASYNC16(sb + (uint32_t)(AF + f * PB + k4 * 4) * 4u,
                   Bg + (size_t)f * E_ + k4 * 4);
    }
    CP_COMMIT();                                        // group0 = A (+extras) + B0

    #pragma unroll 1
    for (int c = 0; c < 8; ++c) {
        __syncthreads();
        if (c + 1 < 8) {
            uint32_t bst = sb + (uint32_t)(AF + ((c + 1) & 1) * BSF) * 4u;
            #pragma unroll
            for (int i = 0; i < 4; ++i) {
                int idx = tid + (i << 9);
                int f = idx >> 3, k4 = idx & 7;
                CP_ASYNC16(bst + (uint32_t)(f * PB + k4 * 4) * 4u,
                           Bg + (size_t)f * E_ + (c + 1) * 32 + k4 * 4);
            }
            CP_COMMIT();
            CP_WAIT1();
        } else {
            CP_WAIT0();
        }
        __syncthreads();

        const uint32_t a_c = a_base + (uint32_t)c * 128u;   // A: global k
        const uint32_t b_c = sb + (uint32_t)(AF + (c & 1) * BSF) * 4u
                           + b_lane;                        // B: k local to stage
        #pragma unroll
        for (int ks = 0; ks < 4; ++ks) {
            uint32_t afr[2][4];
            ldsm_x4(afr[0], a_c + ks * 32u);
            ldsm_x4(afr[1], a_c + 16u * PA * 4u + ks * 32u);
            uint32_t bfr[8][2];
            #pragma unroll
            for (int nt = 0; nt < 8; ++nt)
                ldsm_x2(bfr[nt], b_c + (uint32_t)nt * (8u * PB * 4u) + ks * 32u);
            #pragma unroll
            for (int nt = 0; nt < 8; ++nt) {
                mma_tf32(acc[0][nt], afr[0], bfr[nt]);
                mma_tf32(acc[1][nt], afr[1], bfr[nt]);
            }
        }
    }
}

// ======================= main fused kernel =================================
__global__ void __launch_bounds__(512, 1)
memcell_mma(const float* __restrict__ state, const float* __restrict__ U,
            const float* __restrict__ x, float* __restrict__ out)
{
    extern __shared__ float sm[];
    const int tid  = threadIdx.x;
    const int lane = tid & 31;
    const int wid  = tid >> 5;
    const int grp  = lane >> 2;
    const int tig  = lane & 3;
    const int mwarp = wid >> 2;
    const int nwarp = wid & 3;
    const int row0 = blockIdx.x * 128;
    const uint32_t sb = smem_u32(sm);

    // stage A (state) + x tile (4 rows x 256)
    stage_a(state, row0, sb, tid);
    if (tid < 256)
        CP_ASYNC16(sb + (uint32_t)(XF + tid * 4) * 4u,
                   x + (size_t)(row0 >> 5) * E_ + tid * 4);

    float acc[2][8][4];
    #pragma unroll
    for (int mt = 0; mt < 2; ++mt)
        #pragma unroll
        for (int nt = 0; nt < 8; ++nt)
            #pragma unroll
            for (int q = 0; q < 4; ++q) acc[mt][nt][q] = 0.f;

    tf32_mainloop(U, sb, tid, acc);

    // ---- fused gate from resident A tile: 4 threads per row ----
    {
        int r = tid >> 2, q = tid & 3;
        const float* arow = sm + r * PA;
        const float* xrow = sm + XF + (r >> 5) * 256;
        float dot = 0.f;
        #pragma unroll
        for (int u = 0; u < 16; ++u) {
            int f4 = u * 4 + q;
            float4 av = *reinterpret_cast<const float4*>(arow + f4 * 4);
            float4 xv = *reinterpret_cast<const float4*>(xrow + f4 * 4);
            dot += av.x * xv.x + av.y * xv.y + av.z * xv.z + av.w * xv.w;
        }
        dot += __shfl_xor_sync(0xffffffffu, dot, 1);
        dot += __shfl_xor_sync(0xffffffffu, dot, 2);
        if (q == 0)
            sm[GF + r] = 1.f / (1.f + expf(-(dot + g_xk[row0 + r])));
    }
    __syncthreads();

    // ---- epilogue pass 1: v = s + g*relu(acc + c1 + c2) -> A smem ----
    float* red = sm + REDF;
    float* inv = sm + INVF;
    #pragma unroll
    for (int mt = 0; mt < 2; ++mt) {
        #pragma unroll
        for (int r2 = 0; r2 < 2; ++r2) {
            int rl   = mwarp * 32 + mt * 16 + grp + r2 * 8;
            int grow = row0 + rl;
            float gv = sm[GF + rl];
            const float* c1r = g_c1 + (size_t)(grow >> 5) * E_;
            const float* c2r = g_c2 + (size_t)(rl & 31) * E_;
            float ss = 0.f;
            #pragma unroll
            for (int nt = 0; nt < 8; ++nt) {
                int col = nwarp * 64 + nt * 8 + tig * 2;
                float2 sv  = *reinterpret_cast<float2*>(sm + rl * PA + col);
                float2 c1v = *reinterpret_cast<const float2*>(c1r + col);
                float2 c2v = *reinterpret_cast<const float2*>(c2r + col);
                float d0 = acc[mt][nt][r2 * 2 + 0] + c1v.x + c2v.x;
                float d1 = acc[mt][nt][r2 * 2 + 1] + c1v.y + c2v.y;
                float v0 = sv.x + gv * fmaxf(d0, 0.f);
                float v1 = sv.y + gv * fmaxf(d1, 0.f);
                ss += v0 * v0 + v1 * v1;
                *reinterpret_cast<float2*>(sm + rl * PA + col) = make_float2(v0, v1);
            }
            ss += __shfl_xor_sync(0xffffffffu, ss, 1);
            ss += __shfl_xor_sync(0xffffffffu, ss, 2);
            if (tig == 0) red[rl * 4 + nwarp] = ss;
        }
    }
    __syncthreads();
    if (tid < 128) {
        float s = red[tid * 4] + red[tid * 4 + 1]
                + red[tid * 4 + 2] + red[tid * 4 + 3];
        inv[tid] = 1.f / (sqrtf(s) + 1e-8f);
    }
    __syncthreads();

    // ---- epilogue pass 2: coalesced normalized writeback ----
    #pragma unroll
    for (int i = 0; i < 16; ++i) {
        int idx = tid + (i << 9);
        int r = idx >> 6, c4 = idx & 63;
        float iv = inv[r];
        float4 v = *reinterpret_cast<float4*>(sm + r * PA + c4 * 4);
        v.x *= iv; v.y *= iv; v.z *= iv; v.w *= iv;
        reinterpret_cast<float4*>(out + (size_t)(row0 + r) * E_)[c4] = v;
    }
}

// ======================= c1 via the same MMA mainloop ======================
// g_c1[row][f] = bias[f] + sum_e x[row][e] * W[f][e]
__global__ void __launch_bounds__(512, 1)
c1_mma(const float* __restrict__ x, const float* __restrict__ W,
       const float* __restrict__ bias)
{
    extern __shared__ float sm[];
    const int tid  = threadIdx.x;
    const int lane = tid & 31;
    const int wid  = tid >> 5;
    const int grp  = lane >> 2;
    const int tig  = lane & 3;
    const int mwarp = wid >> 2;
    const int nwarp = wid & 3;
    const int row0 = blockIdx.x * 128;
    const uint32_t sb = smem_u32(sm);

    stage_a(x, row0, sb, tid);
    if (tid < 64)   // bias -> smem (256 floats)
        CP_ASYNC16(sb + (uint32_t)(XF + tid * 4) * 4u, bias + tid * 4);

    float acc[2][8][4];
    #pragma unroll
    for (int mt = 0; mt < 2; ++mt)
        #pragma unroll
        for (int nt = 0; nt < 8; ++nt)
            #pragma unroll
            for (int q = 0; q < 4; ++q) acc[mt][nt][q] = 0.f;

    tf32_mainloop(W, sb, tid, acc);

    #pragma unroll
    for (int mt = 0; mt < 2; ++mt) {
        #pragma unroll
        for (int r2 = 0; r2 < 2; ++r2) {
            int rl  = mwarp * 32 + mt * 16 + grp + r2 * 8;
            int row = row0 + rl;
            #pragma unroll
            for (int nt = 0; nt < 8; ++nt) {
                int col = nwarp * 64 + nt * 8 + tig * 2;
                float2 bv = *reinterpret_cast<const float2*>(sm + XF + col);
                float2 o  = make_float2(acc[mt][nt][r2 * 2 + 0] + bv.x,
                                        acc[mt][nt][r2 * 2 + 1] + bv.y);
                *reinterpret_cast<float2*>(g_c1 + (size_t)row * E_ + col) = o;
            }
        }
    }
}

// ======================= tiny side kernels =================================
__global__ void gemm_c2(const float* __restrict__ keys, const float* __restrict__ V)
{
    __shared__ float ks[E_];
    int j = blockIdx.x;
    int f = threadIdx.x;
    ks[f] = keys[j * E_ + f];
    __syncthreads();
    const float4* vp = reinterpret_cast<const float4*>(V) + (size_t)f * (E_ / 4);
    const float4* kp = reinterpret_cast<const float4*>(ks);
    float a = 0.f;
    #pragma unroll
    for (int e4 = 0; e4 < E_ / 4; ++e4) {
        float4 vv = vp[e4], k = kp[e4];
        a += vv.x * k.x + vv.y * k.y + vv.z * k.z + vv.w * k.w;
    }
    g_c2[j * E_ + f] = a;
}

// xk[b][j] = dot(x_b, key_j)
__global__ void __launch_bounds__(256) xk_kernel(const float* __restrict__ x,
                                                 const float* __restrict__ keys)
{
    __shared__ float4 xs[E_ / 4];
    int b = blockIdx.x, tid = threadIdx.x;
    if (tid < E_ / 4) xs[tid] = reinterpret_cast<const float4*>(x + (size_t)b * E_)[tid];
    __syncthreads();

    int warp = tid >> 5, lane = tid & 31;
    #pragma unroll
    for (int t = 0; t < 4; ++t) {
        int jj = warp + t * 8;
        const float4* kp = reinterpret_cast<const float4*>(keys + (size_t)jj * E_);
        float p = 0.f;
        #pragma unroll
        for (int q = 0; q < 2; ++q) {
            float4 k = kp[lane + 32 * q];
            float4 xv = xs[lane + 32 * q];
            p += xv.x * k.x + xv.y * k.y + xv.z * k.z + xv.w * k.w;
        }
        #pragma unroll
        for (int o = 16; o; o >>= 1) p += __shfl_xor_sync(0xffffffffu, p, o);
        if (lane == 0) g_xk[b * J_ + jj] = p;
    }
}

// ===========================================================================
extern "C" void kernel_launch(void* const* d_in, const int* in_sizes, int n_in,
                              void* d_out, int out_size)
{
    const float* x     = (const float*)d_in[0];
    const float* state = (const float*)d_in[1];
    const float* keys  = (const float*)d_in[2];
    const float* U     = (const float*)d_in[3];
    const float* V     = (const float*)d_in[4];
    const float* W     = (const float*)d_in[5];
    const float* bias  = (const float*)d_in[6];
    float* out = (float*)d_out;

    cudaFuncSetAttribute(c1_mma,      cudaFuncAttributeMaxDynamicSharedMemorySize, MAIN_SMEM);
    cudaFuncSetAttribute(memcell_mma, cudaFuncAttributeMaxDynamicSharedMemorySize, MAIN_SMEM);

    gemm_c2<<<J_, E_>>>(keys, V);
    xk_kernel<<<B_, 256>>>(x, keys);
    c1_mma<<<B_ / 128, 512, MAIN_SMEM>>>(x, W, bias);
    memcell_mma<<<ROWS / 128, 512, MAIN_SMEM>>>(state, U, x, out);
}

// round 8
// speedup vs baseline: 1.0095x; 1.0095x over previous
#include <cuda_runtime.h>
#include <math.h>
#include <stdint.h>

#define B_   4096
#define J_   32
#define E_   256
#define ROWS (B_ * J_)

// ======================= scratch (device globals) ==========================
__device__ float g_c1[B_ * E_];     // bias + x @ W^T
__device__ float g_c2[J_ * E_];     // keys @ V^T
__device__ float g_xk[B_ * J_];     // x . key_j   (raw dot, pre-sigmoid)

// ======================= PTX helpers =======================================
__device__ __forceinline__ uint32_t smem_u32(const void* p) {
    uint32_t a;
    asm("{ .reg .u64 t; cvta.to.shared.u64 t, %1; cvt.u32.u64 %0, t; }"
        : "=r"(a) : "l"(p));
    return a;
}

#define CP_ASYNC16(dst, src)                                                  \
    asm volatile("cp.async.cg.shared.global [%0], [%1], 16;"                  \
        :: "r"(dst), "l"(__cvta_generic_to_global((const void*)(src))) : "memory")
#define CP_COMMIT() asm volatile("cp.async.commit_group;" ::: "memory")
#define CP_WAIT1()  asm volatile("cp.async.wait_group 1;" ::: "memory")
#define CP_WAIT0()  asm volatile("cp.async.wait_group 0;" ::: "memory")

__device__ __forceinline__ void mma_tf32(float* d, const uint32_t* a,
                                         const uint32_t* b) {
    asm volatile(
        "mma.sync.aligned.m16n8k8.row.col.f32.tf32.tf32.f32 "
        "{%0,%1,%2,%3}, {%4,%5,%6,%7}, {%8,%9}, {%0,%1,%2,%3};"
        : "+f"(d[0]), "+f"(d[1]), "+f"(d[2]), "+f"(d[3])
        : "r"(a[0]), "r"(a[1]), "r"(a[2]), "r"(a[3]), "r"(b[0]), "r"(b[1]));
}

__device__ __forceinline__ void ldsm_x4(uint32_t* r, uint32_t addr) {
    asm volatile("ldmatrix.sync.aligned.m8n8.x4.shared.b16 {%0,%1,%2,%3}, [%4];"
        : "=r"(r[0]), "=r"(r[1]), "=r"(r[2]), "=r"(r[3]) : "r"(addr));
}
__device__ __forceinline__ void ldsm_x2(uint32_t* r, uint32_t addr) {
    asm volatile("ldmatrix.sync.aligned.m8n8.x2.shared.b16 {%0,%1}, [%2];"
        : "=r"(r[0]), "=r"(r[1]) : "r"(addr));
}

// ======================= shared GEMM config ================================
// 256 thr (8 warps, 2m x 4n), warp tile 32x64. CTA tile M=64, N=256,
// K=256 in 16 chunks of 16. A resident (pitch 260, raw fp32 -> HW tf32).
// B double-buffered via cp.async (pitch 20, k local to 16-wide stage).
// 111KB smem/CTA -> 2 CTAs/SM for cross-CTA stall overlap.
#define PA    260
#define PB    20
#define AF    16640                  // 64*260 floats; B stages follow
#define BSF   5120                   // 256*20 floats per stage
#define XF    (AF + 2 * BSF)         // 26880 : x tile (2x256) / bias
#define GF    (XF + 512)             // 27392 : gate[64]
#define REDF  (GF + 64)              // 27456 : red[64*4]
#define INVF  (REDF + 256)           // 27712 : inv[64]
#define SMEMF (INVF + 64)            // 27776 floats
#define MAIN_SMEM (SMEMF * 4)        // 111104 bytes

// Stage the 64x256 A tile via cp.async (256 threads).
__device__ __forceinline__ void stage_a(const float* __restrict__ Ag,
                                        int row0, uint32_t sb, int tid)
{
    #pragma unroll
    for (int i = 0; i < 16; ++i) {
        int idx = tid + (i << 8);
        int r = idx >> 6, c4 = idx & 63;
        CP_ASYNC16(sb + (uint32_t)(r * PA + c4 * 4) * 4u,
                   Ag + (size_t)(row0 + r) * E_ + c4 * 4);
    }
}

// Mainloop: acc += A_tile @ Bg^T  (Bg is 256x256 row-major [n][k]).
// Caller must have issued A staging cp.asyncs (uncommitted).
__device__ __forceinline__ void tf32_mainloop(const float* __restrict__ Bg,
    uint32_t sb, int tid, float acc[2][8][4])
{
    const int lane = tid & 31;
    const int wid  = tid >> 5;
    const int mwarp = wid >> 2;       // 0..1 (32 rows)
    const int nwarp = wid & 3;        // 0..3 (64 cols)

    // ldmatrix lane-address bases (bytes)
    const uint32_t a_base = sb
        + (uint32_t)((mwarp * 32 + (lane & 15)) * PA + ((lane >> 4) << 2)) * 4u;
    const uint32_t b_lane =
        (uint32_t)((nwarp * 64 + (lane & 7)) * PB + (((lane >> 3) & 1) << 2)) * 4u;

    #pragma unroll
    for (int i = 0; i < 4; ++i) {                       // B chunk 0 (16 k)
        int idx = tid + (i << 8);
        int f = idx >> 2, k4 = idx & 3;
        CP_ASYNC16(sb + (uint32_t)(AF + f * PB + k4 * 4) * 4u,
                   Bg + (size_t)f * E_ + k4 * 4);
    }
    CP_COMMIT();                                        // group0 = A (+extras) + B0

    #pragma unroll 1
    for (int c = 0; c < 16; ++c) {
        __syncthreads();
        if (c + 1 < 16) {
            uint32_t bst = sb + (uint32_t)(AF + ((c + 1) & 1) * BSF) * 4u;
            #pragma unroll
            for (int i = 0; i < 4; ++i) {
                int idx = tid + (i << 8);
                int f = idx >> 2, k4 = idx & 3;
                CP_ASYNC16(bst + (uint32_t)(f * PB + k4 * 4) * 4u,
                           Bg + (size_t)f * E_ + (c + 1) * 16 + k4 * 4);
            }
            CP_COMMIT();
            CP_WAIT1();
        } else {
            CP_WAIT0();
        }
        __syncthreads();

        const uint32_t a_c = a_base + (uint32_t)c * 64u;    // A: global k (16 fl)
        const uint32_t b_c = sb + (uint32_t)(AF + (c & 1) * BSF) * 4u
                           + b_lane;                        // B: k local to stage
        #pragma unroll
        for (int ks = 0; ks < 2; ++ks) {
            uint32_t afr[2][4];
            ldsm_x4(afr[0], a_c + ks * 32u);
            ldsm_x4(afr[1], a_c + 16u * PA * 4u + ks * 32u);
            uint32_t bfr[8][2];
            #pragma unroll
            for (int nt = 0; nt < 8; ++nt)
                ldsm_x2(bfr[nt], b_c + (uint32_t)nt * (8u * PB * 4u) + ks * 32u);
            #pragma unroll
            for (int nt = 0; nt < 8; ++nt) {
                mma_tf32(acc[0][nt], afr[0], bfr[nt]);
                mma_tf32(acc[1][nt], afr[1], bfr[nt]);
            }
        }
    }
}

// ======================= main fused kernel =================================
__global__ void __launch_bounds__(256, 2)
memcell_mma(const float* __restrict__ state, const float* __restrict__ U,
            const float* __restrict__ x, float* __restrict__ out)
{
    extern __shared__ float sm[];
    const int tid  = threadIdx.x;
    const int lane = tid & 31;
    const int wid  = tid >> 5;
    const int grp  = lane >> 2;
    const int tig  = lane & 3;
    const int mwarp = wid >> 2;
    const int nwarp = wid & 3;
    const int row0 = blockIdx.x * 64;
    const uint32_t sb = smem_u32(sm);

    // stage A (state) + x tile (2 rows x 256)
    stage_a(state, row0, sb, tid);
    if (tid < 128)
        CP_ASYNC16(sb + (uint32_t)(XF + tid * 4) * 4u,
                   x + (size_t)(row0 >> 5) * E_ + tid * 4);

    float acc[2][8][4];
    #pragma unroll
    for (int mt = 0; mt < 2; ++mt)
        #pragma unroll
        for (int nt = 0; nt < 8; ++nt)
            #pragma unroll
            for (int q = 0; q < 4; ++q) acc[mt][nt][q] = 0.f;

    tf32_mainloop(U, sb, tid, acc);

    // ---- fused gate from resident A tile: 4 threads per row ----
    {
        int r = tid >> 2, q = tid & 3;
        const float* arow = sm + r * PA;
        const float* xrow = sm + XF + (r >> 5) * 256;
        float dot = 0.f;
        #pragma unroll
        for (int u = 0; u < 16; ++u) {
            int f4 = u * 4 + q;
            float4 av = *reinterpret_cast<const float4*>(arow + f4 * 4);
            float4 xv = *reinterpret_cast<const float4*>(xrow + f4 * 4);
            dot += av.x * xv.x + av.y * xv.y + av.z * xv.z + av.w * xv.w;
        }
        dot += __shfl_xor_sync(0xffffffffu, dot, 1);
        dot += __shfl_xor_sync(0xffffffffu, dot, 2);
        if (q == 0)
            sm[GF + r] = 1.f / (1.f + expf(-(dot + g_xk[row0 + r])));
    }
    __syncthreads();

    // ---- epilogue pass 1: v = s + g*relu(acc + c1 + c2) -> A smem ----
    float* red = sm + REDF;
    float* inv = sm + INVF;
    #pragma unroll
    for (int mt = 0; mt < 2; ++mt) {
        #pragma unroll
        for (int r2 = 0; r2 < 2; ++r2) {
            int rl   = mwarp * 32 + mt * 16 + grp + r2 * 8;
            int grow = row0 + rl;
            float gv = sm[GF + rl];
            const float* c1r = g_c1 + (size_t)(grow >> 5) * E_;
            const float* c2r = g_c2 + (size_t)(grow & 31) * E_;
            float ss = 0.f;
            #pragma unroll
            for (int nt = 0; nt < 8; ++nt) {
                int col = nwarp * 64 + nt * 8 + tig * 2;
                float2 sv  = *reinterpret_cast<float2*>(sm + rl * PA + col);
                float2 c1v = *reinterpret_cast<const float2*>(c1r + col);
                float2 c2v = *reinterpret_cast<const float2*>(c2r + col);
                float d0 = acc[mt][nt][r2 * 2 + 0] + c1v.x + c2v.x;
                float d1 = acc[mt][nt][r2 * 2 + 1] + c1v.y + c2v.y;
                float v0 = sv.x + gv * fmaxf(d0, 0.f);
                float v1 = sv.y + gv * fmaxf(d1, 0.f);
                ss += v0 * v0 + v1 * v1;
                *reinterpret_cast<float2*>(sm + rl * PA + col) = make_float2(v0, v1);
            }
            ss += __shfl_xor_sync(0xffffffffu, ss, 1);
            ss += __shfl_xor_sync(0xffffffffu, ss, 2);
            if (tig == 0) red[rl * 4 + nwarp] = ss;
        }
    }
    __syncthreads();
    if (tid < 64) {
        float s = red[tid * 4] + red[tid * 4 + 1]
                + red[tid * 4 + 2] + red[tid * 4 + 3];
        inv[tid] = 1.f / (sqrtf(s) + 1e-8f);
    }
    __syncthreads();

    // ---- epilogue pass 2: coalesced normalized writeback ----
    #pragma unroll
    for (int i = 0; i < 16; ++i) {
        int idx = tid + (i << 8);
        int r = idx >> 6, c4 = idx & 63;
        float iv = inv[r];
        float4 v = *reinterpret_cast<float4*>(sm + r * PA + c4 * 4);
        v.x *= iv; v.y *= iv; v.z *= iv; v.w *= iv;
        reinterpret_cast<float4*>(out + (size_t)(row0 + r) * E_)[c4] = v;
    }
}

// ======================= c1 via the same MMA mainloop ======================
// g_c1[row][f] = bias[f] + sum_e x[row][e] * W[f][e]
__global__ void __launch_bounds__(256, 2)
c1_mma(const float* __restrict__ x, const float* __restrict__ W,
       const float* __restrict__ bias)
{
    extern __shared__ float sm[];
    const int tid  = threadIdx.x;
    const int lane = tid & 31;
    const int wid  = tid >> 5;
    const int grp  = lane >> 2;
    const int tig  = lane & 3;
    const int mwarp = wid >> 2;
    const int nwarp = wid & 3;
    const int row0 = blockIdx.x * 64;
    const uint32_t sb = smem_u32(sm);

    stage_a(x, row0, sb, tid);
    if (tid < 64)   // bias -> smem (256 floats)
        CP_ASYNC16(sb + (uint32_t)(XF + tid * 4) * 4u, bias + tid * 4);

    float acc[2][8][4];
    #pragma unroll
    for (int mt = 0; mt < 2; ++mt)
        #pragma unroll
        for (int nt = 0; nt < 8; ++nt)
            #pragma unroll
            for (int q = 0; q < 4; ++q) acc[mt][nt][q] = 0.f;

    tf32_mainloop(W, sb, tid, acc);

    #pragma unroll
    for (int mt = 0; mt < 2; ++mt) {
        #pragma unroll
        for (int r2 = 0; r2 < 2; ++r2) {
            int rl  = mwarp * 32 + mt * 16 + grp + r2 * 8;
            int row = row0 + rl;
            #pragma unroll
            for (int nt = 0; nt < 8; ++nt) {
                int col = nwarp * 64 + nt * 8 + tig * 2;
                float2 bv = *reinterpret_cast<const float2*>(sm + XF + col);
                float2 o  = make_float2(acc[mt][nt][r2 * 2 + 0] + bv.x,
                                        acc[mt][nt][r2 * 2 + 1] + bv.y);
                *reinterpret_cast<float2*>(g_c1 + (size_t)row * E_ + col) = o;
            }
        }
    }
}

// ======================= tiny side kernels =================================
__global__ void gemm_c2(const float* __restrict__ keys, const float* __restrict__ V)
{
    __shared__ float ks[E_];
    int j = blockIdx.x;
    int f = threadIdx.x;
    ks[f] = keys[j * E_ + f];
    __syncthreads();
    const float4* vp = reinterpret_cast<const float4*>(V) + (size_t)f * (E_ / 4);
    const float4* kp = reinterpret_cast<const float4*>(ks);
    float a = 0.f;
    #pragma unroll
    for (int e4 = 0; e4 < E_ / 4; ++e4) {
        float4 vv = vp[e4], k = kp[e4];
        a += vv.x * k.x + vv.y * k.y + vv.z * k.z + vv.w * k.w;
    }
    g_c2[j * E_ + f] = a;
}

// xk[b][j] = dot(x_b, key_j)
__global__ void __launch_bounds__(256) xk_kernel(const float* __restrict__ x,
                                                 const float* __restrict__ keys)
{
    __shared__ float4 xs[E_ / 4];
    int b = blockIdx.x, tid = threadIdx.x;
    if (tid < E_ / 4) xs[tid] = reinterpret_cast<const float4*>(x + (size_t)b * E_)[tid];
    __syncthreads();

    int warp = tid >> 5, lane = tid & 31;
    #pragma unroll
    for (int t = 0; t < 4; ++t) {
        int jj = warp + t * 8;
        const float4* kp = reinterpret_cast<const float4*>(keys + (size_t)jj * E_);
        float p = 0.f;
        #pragma unroll
        for (int q = 0; q < 2; ++q) {
            float4 k = kp[lane + 32 * q];
            float4 xv = xs[lane + 32 * q];
            p += xv.x * k.x + xv.y * k.y + xv.z * k.z + xv.w * k.w;
        }
        #pragma unroll
        for (int o = 16; o; o >>= 1) p += __shfl_xor_sync(0xffffffffu, p, o);
        if (lane == 0) g_xk[b * J_ + jj] = p;
    }
}

// ===========================================================================
extern "C" void kernel_launch(void* const* d_in, const int* in_sizes, int n_in,
                              void* d_out, int out_size)
{
    const float* x     = (const float*)d_in[0];
    const float* state = (const float*)d_in[1];
    const float* keys  = (const float*)d_in[2];
    const float* U     = (const float*)d_in[3];
    const float* V     = (const float*)d_in[4];
    const float* W     = (const float*)d_in[5];
    const float* bias  = (const float*)d_in[6];
    float* out = (float*)d_out;

    cudaFuncSetAttribute(c1_mma,      cudaFuncAttributeMaxDynamicSharedMemorySize, MAIN_SMEM);
    cudaFuncSetAttribute(memcell_mma, cudaFuncAttributeMaxDynamicSharedMemorySize, MAIN_SMEM);

    gemm_c2<<<J_, E_>>>(keys, V);
    xk_kernel<<<B_, 256>>>(x, keys);
    c1_mma<<<B_ / 64, 256, MAIN_SMEM>>>(x, W, bias);
    memcell_mma<<<ROWS / 64, 256, MAIN_SMEM>>>(state, U, x, out);
}